// round 4
// baseline (speedup 1.0000x reference)
#include <cuda_runtime.h>

// LSTM_60808146977081: B=4096, T=512, I=10, H=32, fp32.
// One warp per batch element; lane = hidden unit. Weights register-resident.
// Recurrent + input gate math via packed fma.rn.f32x2 (sm_103a FFMA2).
// h broadcast per step via smem (STS + LDS.128 broadcast), double-buffered,
// one __syncwarp per step. x prefetched one timestep ahead.

#define FULL_MASK 0xFFFFFFFFu

__device__ __forceinline__ float2 ffma2(float2 a, float2 b, float2 c) {
    union F2U { float2 f; unsigned long long u; };
    F2U ua, ub, uc, ud;
    ua.f = a; ub.f = b; uc.f = c;
    asm("fma.rn.f32x2 %0, %1, %2, %3;"
        : "=l"(ud.u) : "l"(ua.u), "l"(ub.u), "l"(uc.u));
    return ud.f;
}

__device__ __forceinline__ float sigmoid_fast(float x) {
    // exp(-x) overflows to +inf for very negative x -> 1/(1+inf) = 0. Safe.
    return __fdividef(1.0f, 1.0f + __expf(-x));
}

__device__ __forceinline__ float tanh_fast(float x) {
    // tanh(|x|) = (1 - e^{-2|x|}) / (1 + e^{-2|x|}), e in (0,1] -> no overflow.
    float e = __expf(-2.0f * fabsf(x));
    float r = __fdividef(1.0f - e, 1.0f + e);
    return copysignf(r, x);
}

__global__ void __launch_bounds__(128)
lstm_warp_per_batch(const float* __restrict__ x,
                    const float* __restrict__ h0,
                    const float* __restrict__ c0,
                    const float* __restrict__ W_ih,
                    const float* __restrict__ W_hh,
                    const float* __restrict__ b_ih,
                    const float* __restrict__ b_hh,
                    const float* __restrict__ W_lin,
                    const float* __restrict__ b_lin,
                    float* __restrict__ out)
{
    constexpr int T = 512;
    constexpr int I = 10;

    const int warp = threadIdx.x >> 5;
    const int lane = threadIdx.x & 31;
    const int b    = blockIdx.x * 4 + warp;

    __shared__ float sh[4][2][32];   // per-warp h broadcast, double-buffered

    // ---- Load weights into registers (one-time, L2-resident after 1st touch) ----
    float2 wh[4][16];   // W_hh rows (gate g*32+lane), packed pairs along j
    float2 wi[4][5];    // W_ih rows, packed pairs along i
    float  bias[4];
#pragma unroll
    for (int g = 0; g < 4; g++) {
        const int r = g * 32 + lane;
        const float2* whp = reinterpret_cast<const float2*>(W_hh + r * 32);
#pragma unroll
        for (int p = 0; p < 16; p++) wh[g][p] = whp[p];
        const float2* wip = reinterpret_cast<const float2*>(W_ih + r * I);
#pragma unroll
        for (int q = 0; q < 5; q++) wi[g][q] = wip[q];
        bias[g] = b_ih[r] + b_hh[r];
    }
    const float wl = W_lin[lane];

    float h = h0[b * 32 + lane];
    float c = c0[b * 32 + lane];

    const float2* xw = reinterpret_cast<const float2*>(x + (size_t)b * (T * I));
    float2 xc[5], xn[5];
#pragma unroll
    for (int q = 0; q < 5; q++) xc[q] = xw[q];

#pragma unroll 2
    for (int t = 0; t < T; t++) {
        const int buf = t & 1;
        sh[warp][buf][lane] = h;
        __syncwarp();

        // Prefetch next timestep's x (clamped at the end; value unused then)
        const float2* nxt = xw + (size_t)(t < T - 1 ? t + 1 : t) * 5;
#pragma unroll
        for (int q = 0; q < 5; q++) xn[q] = nxt[q];

        float2 acc[4];
#pragma unroll
        for (int g = 0; g < 4; g++) acc[g] = make_float2(bias[g], 0.0f);

        // Recurrent: gates += W_hh[row] . h  (h broadcast from smem, paired)
        const float4* hp4 = reinterpret_cast<const float4*>(sh[warp][buf]);
#pragma unroll
        for (int p = 0; p < 8; p++) {
            const float4 hv = hp4[p];
            const float2 ha = make_float2(hv.x, hv.y);
            const float2 hb = make_float2(hv.z, hv.w);
#pragma unroll
            for (int g = 0; g < 4; g++) {
                acc[g] = ffma2(wh[g][2 * p],     ha, acc[g]);
                acc[g] = ffma2(wh[g][2 * p + 1], hb, acc[g]);
            }
        }
        // Input: gates += W_ih[row] . x_t
#pragma unroll
        for (int q = 0; q < 5; q++) {
#pragma unroll
            for (int g = 0; g < 4; g++)
                acc[g] = ffma2(wi[g][q], xc[q], acc[g]);
        }

        const float gi = acc[0].x + acc[0].y;
        const float gf = acc[1].x + acc[1].y;
        const float gg = acc[2].x + acc[2].y;
        const float go = acc[3].x + acc[3].y;

        const float ig = sigmoid_fast(gi);
        const float fg = sigmoid_fast(gf);
        const float gc = tanh_fast(gg);
        const float og = sigmoid_fast(go);

        c = fg * c + ig * gc;
        h = og * tanh_fast(c);

#pragma unroll
        for (int q = 0; q < 5; q++) xc[q] = xn[q];
    }

    // out[b] = sum_k h[k] * W_lin[0,k] + b_lin
    float v = h * wl;
#pragma unroll
    for (int off = 16; off; off >>= 1)
        v += __shfl_xor_sync(FULL_MASK, v, off);
    if (lane == 0) out[b] = v + b_lin[0];
}

extern "C" void kernel_launch(void* const* d_in, const int* in_sizes, int n_in,
                              void* d_out, int out_size)
{
    const float* x     = (const float*)d_in[0];
    const float* h0    = (const float*)d_in[1];
    const float* c0    = (const float*)d_in[2];
    const float* W_ih  = (const float*)d_in[3];
    const float* W_hh  = (const float*)d_in[4];
    const float* b_ih  = (const float*)d_in[5];
    const float* b_hh  = (const float*)d_in[6];
    const float* W_lin = (const float*)d_in[7];
    const float* b_lin = (const float*)d_in[8];
    float* out = (float*)d_out;

    // 4096 batches, 4 warps (batches) per 128-thread block -> 1024 blocks
    lstm_warp_per_batch<<<1024, 128>>>(x, h0, c0, W_ih, W_hh, b_ih, b_hh,
                                       W_lin, b_lin, out);
}